// round 11
// baseline (speedup 1.0000x reference)
#include <cuda_runtime.h>
#include <cuda_fp16.h>
#include <math.h>
#include <stdint.h>

#define TT 512
#define NN 1024
#define DD 256
#define M_ROWS (TT * NN)

__device__ float g_e[M_ROWS];
__device__ __align__(16) __half g_Whi[DD * DD];
// attend scan carry (online-softmax state across chunk kernels)
__device__ float g_m[NN];
__device__ float g_s[NN];
__device__ float g_num[NN * DD];

// ---------------------------------------------------------------------------
// SMEM (per CTA, 54272 B -> 2 CTAs/SM). 80B rows (32 halves + 16B pad).
// ---------------------------------------------------------------------------
#define SB(buf)    ((buf) * 20480)
#define SA(buf)    (40960 + (buf) * 5120)
#define SBIAS      51200
#define SSW        52224
#define SRED       53248
#define SMTOT      54272

// ---------------------------------------------------------------------------
// PTX helpers (baseline ISA only -- toolchain targets sm_103, no tcgen05)
// ---------------------------------------------------------------------------
__device__ __forceinline__ uint32_t smem_u32(const void* p) {
    uint32_t a;
    asm("{ .reg .u64 t; cvta.to.shared.u64 t, %1; cvt.u32.u64 %0, t; }"
        : "=r"(a) : "l"(p));
    return a;
}
__device__ __forceinline__ void cp_async16(uint32_t dst, const void* src) {
    asm volatile("cp.async.cg.shared.global [%0], [%1], 16;"
                 :: "r"(dst), "l"(src) : "memory");
}
#define CP_COMMIT() asm volatile("cp.async.commit_group;" ::: "memory")
#define CP_WAIT(n)  asm volatile("cp.async.wait_group %0;" :: "n"(n) : "memory")

__device__ __forceinline__ void ldsm4(uint32_t* r, uint32_t addr) {
    asm volatile("ldmatrix.sync.aligned.m8n8.x4.shared.b16 {%0,%1,%2,%3}, [%4];"
                 : "=r"(r[0]), "=r"(r[1]), "=r"(r[2]), "=r"(r[3]) : "r"(addr));
}
__device__ __forceinline__ void mma16816(float* c, const uint32_t* a,
                                         uint32_t b0, uint32_t b1) {
    asm volatile(
        "mma.sync.aligned.m16n8k16.row.col.f32.f16.f16.f32 "
        "{%0,%1,%2,%3}, {%4,%5,%6,%7}, {%8,%9}, {%0,%1,%2,%3};"
        : "+f"(c[0]), "+f"(c[1]), "+f"(c[2]), "+f"(c[3])
        : "r"(a[0]), "r"(a[1]), "r"(a[2]), "r"(a[3]), "r"(b0), "r"(b1));
}

// fp32 x8 -> fp16 x8
__device__ __forceinline__ uint4 cvt8hi(const float4& u, const float4& v) {
    __half2 h0 = __floats2half2_rn(u.x, u.y);
    __half2 h1 = __floats2half2_rn(u.z, u.w);
    __half2 h2 = __floats2half2_rn(v.x, v.y);
    __half2 h3 = __floats2half2_rn(v.z, v.w);
    uint4 hi;
    hi.x = *(uint32_t*)&h0; hi.y = *(uint32_t*)&h1;
    hi.z = *(uint32_t*)&h2; hi.w = *(uint32_t*)&h3;
    return hi;
}

// tanh via MUFU (EX2 + RCP), rel err ~1e-6
__device__ __forceinline__ float tanh_mufu(float z) {
    float u = __expf(2.0f * z);
    return 1.0f - __fdividef(2.0f, u + 1.0f);
}

// ---------------------------------------------------------------------------
__global__ void w_prep(const float* __restrict__ W) {
    int i = blockIdx.x * blockDim.x + threadIdx.x;
    const float4* p = reinterpret_cast<const float4*>(W) + i * 2;
    reinterpret_cast<uint4*>(g_Whi)[i] = cvt8hi(p[0], p[1]);
}

// ---------------------------------------------------------------------------
// Kernel A: fp16 HMMA GEMM, BM=64 x BN=256, 256 threads, 2 CTAs/SM.
// Inner loop: flat 8-group (ks x ntp) stream with double-buffered B
// fragments so each group's LDSM latency hides under the previous group's
// MMA pipe time.
// ---------------------------------------------------------------------------
__global__ __launch_bounds__(256, 2)
void gemm_score_hmma(const float* __restrict__ H,
                     const float* __restrict__ bias,
                     const float* __restrict__ swt,
                     int blk0)
{
    extern __shared__ char smem[];
    const uint32_t sb = smem_u32(smem);
    const int tid  = threadIdx.x;
    const int lane = tid & 31;
    const int warp = tid >> 5;          // 0..7
    const int wr   = warp >> 2;         // 0..1: rows 32*wr
    const int wc   = warp & 3;          // 0..3: cols 64*wc
    const int row0 = (blockIdx.x + blk0) * 64;

    if (tid < 256) {
        ((float*)(smem + SBIAS))[tid] = bias[tid];
        ((float*)(smem + SSW))[tid]   = swt[tid];
    }

    // A loader: 64 rows x 4 ksegs = 256 slots, one per thread
    const int arow  = tid >> 2;
    const int akseg = tid & 3;
    const float* aptr = H + (size_t)(row0 + arow) * DD + akseg * 8;
    const uint32_t a_sts = (uint32_t)(arow * 80 + akseg * 16);

    float acc[2][8][4];
    #pragma unroll
    for (int m = 0; m < 2; m++)
        #pragma unroll
        for (int n = 0; n < 8; n++)
            #pragma unroll
            for (int e = 0; e < 4; e++) acc[m][n][e] = 0.0f;

    // B cp.async: 1024 x 16B per chunk -> 4 per thread
    auto cpB = [&](int c, int buf) {
        #pragma unroll
        for (int p = 0; p < 4; p++) {
            int idx = tid + p * 256;
            int r   = idx >> 2;
            int ch  = idx & 3;
            cp_async16(sb + SB(buf) + r * 80 + ch * 16,
                       g_Whi + (size_t)r * DD + c * 32 + ch * 8);
        }
        CP_COMMIT();
    };

    // ldmatrix lane addressing
    const int lrow = lane & 15;
    const int lkh  = lane >> 4;
    const uint32_t aAddr = sb + 40960u +
                           (uint32_t)((wr * 32 + lrow) * 80 + lkh * 16);
    const uint32_t bAddr = sb + (uint32_t)((wc * 64 + lrow) * 80 + lkh * 16);

    // ---- prologue ----
    float4 ar0, ar1;
    cpB(0, 0);
    ar0 = *reinterpret_cast<const float4*>(aptr);
    ar1 = *reinterpret_cast<const float4*>(aptr + 4);
    *reinterpret_cast<uint4*>(smem + SA(0) + a_sts) = cvt8hi(ar0, ar1);
    ar0 = *reinterpret_cast<const float4*>(aptr + 32);
    ar1 = *reinterpret_cast<const float4*>(aptr + 36);
    CP_WAIT(0);
    __syncthreads();

    #pragma unroll
    for (int c = 0; c < 8; c++) {
        const int buf = c & 1;
        if (c < 7) {
            cpB(c + 1, buf ^ 1);
            *reinterpret_cast<uint4*>(smem + SA(buf ^ 1) + a_sts) =
                cvt8hi(ar0, ar1);
        }
        if (c < 6) {
            ar0 = *reinterpret_cast<const float4*>(aptr + (c + 2) * 32);
            ar1 = *reinterpret_cast<const float4*>(aptr + (c + 2) * 32 + 4);
        }

        // ---- MMA chunk c: flat pipelined (ks, ntp) stream ----
        const uint32_t aA = aAddr + (uint32_t)(buf * 5120);
        const uint32_t bB = bAddr + (uint32_t)SB(buf);

        uint32_t ah[2][4];
        uint32_t bf[2][4];
        ldsm4(ah[0], aA);                 // ks=0 A fragments
        ldsm4(ah[1], aA + 16 * 80);
        ldsm4(bf[0], bB);                 // group 0 B fragment

        #pragma unroll
        for (int g = 0; g < 8; g++) {
            const int ntp = g & 3;
            // prefetch next group's B fragment under this group's MMAs
            if (g < 7) {
                const int ng = g + 1;
                ldsm4(bf[ng & 1],
                      bB + (ng & 3) * (16 * 80) + (ng >> 2) * 32);
            }
            // reload A fragments at the ks boundary (used from g=4)
            if (g == 4) {
                ldsm4(ah[0], aA + 32);
                ldsm4(ah[1], aA + 16 * 80 + 32);
            }
            uint32_t* f = bf[g & 1];
            mma16816(acc[0][ntp * 2 + 0], ah[0], f[0], f[2]);
            mma16816(acc[0][ntp * 2 + 1], ah[0], f[1], f[3]);
            mma16816(acc[1][ntp * 2 + 0], ah[1], f[0], f[2]);
            mma16816(acc[1][ntp * 2 + 1], ah[1], f[1], f[3]);
        }

        if (c < 7) {
            CP_WAIT(0);
            __syncthreads();
        }
    }

    // ---- epilogue: MUFU tanh + score reduce over 256 e-columns ----
    const float* sbias = (const float*)(smem + SBIAS);
    const float* ssw   = (const float*)(smem + SSW);
    float* sred        = (float*)(smem + SRED);

    #pragma unroll
    for (int mt = 0; mt < 2; mt++) {
        #pragma unroll
        for (int h = 0; h < 2; h++) {
            float part = 0.0f;
            const int lrow_out = wr * 32 + mt * 16 + (lane >> 2) + h * 8;
            #pragma unroll
            for (int nt = 0; nt < 8; nt++) {
                const int col = wc * 64 + nt * 8 + (lane & 3) * 2;
                float2 bb = *reinterpret_cast<const float2*>(&sbias[col]);
                float2 ws = *reinterpret_cast<const float2*>(&ssw[col]);
                part = fmaf(tanh_mufu(acc[mt][nt][h * 2 + 0] + bb.x), ws.x, part);
                part = fmaf(tanh_mufu(acc[mt][nt][h * 2 + 1] + bb.y), ws.y, part);
            }
            part += __shfl_xor_sync(0xffffffffu, part, 1);
            part += __shfl_xor_sync(0xffffffffu, part, 2);
            if ((lane & 3) == 0) sred[wc * 64 + lrow_out] = part;
        }
    }
    __syncthreads();
    if (tid < 64)
        g_e[row0 + tid] = (sred[tid] + sred[64 + tid]) +
                          (sred[128 + tid] + sred[192 + tid]);
}

// ---------------------------------------------------------------------------
// Kernel B: chunked causal softmax prefix average with carried scan state.
// ---------------------------------------------------------------------------
__global__ __launch_bounds__(256)
void attend_chunk(const float* __restrict__ H, float* __restrict__ C,
                  int t0, int t1, int first)
{
    __shared__ float sal[80];   // alpha (rescale of old state)
    __shared__ float sp[80];    // p = exp(e - m_new)
    __shared__ float siv[80];   // 1/s after step

    const int n   = blockIdx.x;
    const int tid = threadIdx.x;
    const int len = t1 - t0;

    if (tid < len)
        sal[tid] = g_e[(size_t)(t0 + tid) * NN + n];
    __syncthreads();

    if (tid == 0) {
        float m = first ? -INFINITY : g_m[n];
        float s = first ? 0.0f      : g_s[n];
        for (int i = 0; i < len; i++) {
            float e  = sal[i];
            float mn = fmaxf(m, e);
            float a  = __expf(m - mn);
            float p  = __expf(e - mn);
            s = s * a + p;
            sal[i] = a;
            sp[i]  = p;
            siv[i] = __fdividef(1.0f, s);
            m = mn;
        }
        g_m[n] = m;
        g_s[n] = s;
    }
    __syncthreads();

    const size_t stride = (size_t)NN * DD;
    const float* hp = H + (size_t)(t0) * stride + (size_t)n * DD + tid;
    float*       cp = C + (size_t)(t0) * stride + (size_t)n * DD + tid;

    float num = first ? 0.0f : g_num[n * DD + tid];
    #pragma unroll 4
    for (int i = 0; i < len; i++) {
        float h = __ldcs(hp + (size_t)i * stride);
        num = fmaf(num, sal[i], sp[i] * h);
        __stcs(cp + (size_t)i * stride, num * siv[i]);
    }
    g_num[n * DD + tid] = num;
}

// ---------------------------------------------------------------------------
// Stream/event plumbing (global ctor; no device-memory APIs).
// ---------------------------------------------------------------------------
#define NCHUNK 8
namespace {
struct Plumbing {
    cudaStream_t s2;
    cudaEvent_t  evG[NCHUNK];
    cudaEvent_t  evJ;
    Plumbing() {
        int lo = 0, hi = 0;
        cudaDeviceGetStreamPriorityRange(&lo, &hi);
        cudaStreamCreateWithPriority(&s2, cudaStreamNonBlocking, hi);
        for (int i = 0; i < NCHUNK; i++)
            cudaEventCreateWithFlags(&evG[i], cudaEventDisableTiming);
        cudaEventCreateWithFlags(&evJ, cudaEventDisableTiming);
    }
};
Plumbing g_plumb;
}

static const int kBlk[NCHUNK + 1] =
    {0, 1184, 2368, 3552, 4736, 5920, 7104, 7936, 8192};

// ---------------------------------------------------------------------------
extern "C" void kernel_launch(void* const* d_in, const int* in_sizes, int n_in,
                              void* d_out, int out_size)
{
    const float* H  = (const float*)d_in[0];
    const float* W  = (const float*)d_in[1];
    const float* b  = (const float*)d_in[2];
    const float* sv = (const float*)d_in[3];
    float* C = (float*)d_out;

    cudaFuncSetAttribute(gemm_score_hmma,
                         cudaFuncAttributeMaxDynamicSharedMemorySize, SMTOT);

    w_prep<<<16, 512>>>(W);

    for (int c = 0; c < NCHUNK; c++) {
        gemm_score_hmma<<<kBlk[c + 1] - kBlk[c], 256, SMTOT>>>(H, b, sv, kBlk[c]);
        cudaEventRecord(g_plumb.evG[c], 0);
    }
    for (int c = 0; c < NCHUNK; c++) {
        cudaStreamWaitEvent(g_plumb.s2, g_plumb.evG[c], 0);
        attend_chunk<<<NN, 256, 0, g_plumb.s2>>>(H, C, kBlk[c] / 16,
                                                 kBlk[c + 1] / 16, c == 0);
    }
    cudaEventRecord(g_plumb.evJ, g_plumb.s2);
    cudaStreamWaitEvent(0, g_plumb.evJ, 0);
}

// round 12
// speedup vs baseline: 1.0287x; 1.0287x over previous
#include <cuda_runtime.h>
#include <cuda_fp16.h>
#include <math.h>
#include <stdint.h>

#define TT 512
#define NN 1024
#define DD 256
#define M_ROWS (TT * NN)

__device__ float g_e[M_ROWS];
__device__ __align__(16) __half g_Whi[DD * DD];
// attend scan carry (online-softmax state across chunk kernels)
__device__ float g_m[NN];
__device__ float g_s[NN];
__device__ float g_num[NN * DD];

// ---------------------------------------------------------------------------
// SMEM (per CTA, 57344 B -> 3 CTAs/SM = 168 KB of 228 KB).
//   A resident: 64 rows * 528 B (256 fp16 = 512 + 16 pad; 4r%32 banks clean)
//   B stream:   2 bufs * 128 rows * 80 B
// ---------------------------------------------------------------------------
#define SA_OFF  0
#define SA_ROW  528
#define SB_OFF  33792
#define SB_SZ   10240
#define SBIAS   54272
#define SSW     55296
#define SRED    56320
#define SMTOT   57344

// ---------------------------------------------------------------------------
// PTX helpers (baseline ISA only -- toolchain targets sm_103, no tcgen05)
// ---------------------------------------------------------------------------
__device__ __forceinline__ uint32_t smem_u32(const void* p) {
    uint32_t a;
    asm("{ .reg .u64 t; cvta.to.shared.u64 t, %1; cvt.u32.u64 %0, t; }"
        : "=r"(a) : "l"(p));
    return a;
}
__device__ __forceinline__ void cp_async16(uint32_t dst, const void* src) {
    asm volatile("cp.async.cg.shared.global [%0], [%1], 16;"
                 :: "r"(dst), "l"(src) : "memory");
}
#define CP_COMMIT() asm volatile("cp.async.commit_group;" ::: "memory")
#define CP_WAIT(n)  asm volatile("cp.async.wait_group %0;" :: "n"(n) : "memory")

__device__ __forceinline__ void ldsm4(uint32_t* r, uint32_t addr) {
    asm volatile("ldmatrix.sync.aligned.m8n8.x4.shared.b16 {%0,%1,%2,%3}, [%4];"
                 : "=r"(r[0]), "=r"(r[1]), "=r"(r[2]), "=r"(r[3]) : "r"(addr));
}
__device__ __forceinline__ void mma16816(float* c, const uint32_t* a,
                                         uint32_t b0, uint32_t b1) {
    asm volatile(
        "mma.sync.aligned.m16n8k16.row.col.f32.f16.f16.f32 "
        "{%0,%1,%2,%3}, {%4,%5,%6,%7}, {%8,%9}, {%0,%1,%2,%3};"
        : "+f"(c[0]), "+f"(c[1]), "+f"(c[2]), "+f"(c[3])
        : "r"(a[0]), "r"(a[1]), "r"(a[2]), "r"(a[3]), "r"(b0), "r"(b1));
}

// fp32 x8 -> fp16 x8
__device__ __forceinline__ uint4 cvt8hi(const float4& u, const float4& v) {
    __half2 h0 = __floats2half2_rn(u.x, u.y);
    __half2 h1 = __floats2half2_rn(u.z, u.w);
    __half2 h2 = __floats2half2_rn(v.x, v.y);
    __half2 h3 = __floats2half2_rn(v.z, v.w);
    uint4 hi;
    hi.x = *(uint32_t*)&h0; hi.y = *(uint32_t*)&h1;
    hi.z = *(uint32_t*)&h2; hi.w = *(uint32_t*)&h3;
    return hi;
}

// tanh via MUFU (EX2 + RCP), rel err ~1e-6
__device__ __forceinline__ float tanh_mufu(float z) {
    float u = __expf(2.0f * z);
    return 1.0f - __fdividef(2.0f, u + 1.0f);
}

// ---------------------------------------------------------------------------
__global__ void w_prep(const float* __restrict__ W) {
    int i = blockIdx.x * blockDim.x + threadIdx.x;
    const float4* p = reinterpret_cast<const float4*>(W) + i * 2;
    reinterpret_cast<uint4*>(g_Whi)[i] = cvt8hi(p[0], p[1]);
}

// ---------------------------------------------------------------------------
// Kernel A: fp16 HMMA GEMM, BM=64 x BN=256 in two 128-col passes.
// 256 threads, 3 CTAs/SM. A resident fp16 in SMEM; B streamed per pass.
// 8 warps: wr = warp&1 (row group of 32), wc = warp>>1 (col group of 32).
// ---------------------------------------------------------------------------
__global__ __launch_bounds__(256, 3)
void gemm_score_hmma(const float* __restrict__ H,
                     const float* __restrict__ bias,
                     const float* __restrict__ swt,
                     int blk0)
{
    extern __shared__ char smem[];
    const uint32_t sb = smem_u32(smem);
    const int tid  = threadIdx.x;
    const int lane = tid & 31;
    const int warp = tid >> 5;          // 0..7
    const int wr   = warp & 1;          // row group 32*wr
    const int wc   = warp >> 1;         // col group 32*wc (within pass)
    const int row0 = (blockIdx.x + blk0) * 64;

    ((float*)(smem + SBIAS))[tid] = bias[tid];
    ((float*)(smem + SSW))[tid]   = swt[tid];

    const int lrow = lane & 15;
    const int lkh  = lane >> 4;
    const uint32_t aAddr = sb + SA_OFF +
                           (uint32_t)((wr * 32 + lrow) * SA_ROW + lkh * 16);
    const uint32_t bAddr = sb + SB_OFF +
                           (uint32_t)((wc * 32 + lrow) * 80 + lkh * 16);

    const float* sbias = (const float*)(smem + SBIAS);
    const float* ssw   = (const float*)(smem + SSW);

    float partAcc[2][2] = {{0.0f, 0.0f}, {0.0f, 0.0f}};

    #pragma unroll 1
    for (int pass = 0; pass < 2; pass++) {
        const __half* Bsrc = g_Whi + (size_t)pass * 128 * DD;

        // B cp.async: 512 x 16B per chunk -> 2 per thread
        auto cpB = [&](int c, int buf) {
            #pragma unroll
            for (int p = 0; p < 2; p++) {
                int idx = tid + p * 256;
                int r   = idx >> 2;
                int ch  = idx & 3;
                cp_async16(sb + SB_OFF + buf * SB_SZ + r * 80 + ch * 16,
                           Bsrc + (size_t)r * DD + c * 32 + ch * 8);
            }
            CP_COMMIT();
        };

        cpB(0, 0);
        if (pass == 0) {
            // A convert: 64 rows x 256 k -> fp16 SMEM (8 slots of 8 elems)
            #pragma unroll
            for (int i = 0; i < 8; i++) {
                int slot = tid + i * 256;
                int r    = slot >> 5;
                int kseg = slot & 31;
                const float* src = H + (size_t)(row0 + r) * DD + kseg * 8;
                float4 u = *reinterpret_cast<const float4*>(src);
                float4 v = *reinterpret_cast<const float4*>(src + 4);
                *reinterpret_cast<uint4*>(smem + SA_OFF + r * SA_ROW +
                                          kseg * 16) = cvt8hi(u, v);
            }
        }
        CP_WAIT(0);
        __syncthreads();

        float acc[2][4][4];
        #pragma unroll
        for (int m = 0; m < 2; m++)
            #pragma unroll
            for (int j = 0; j < 4; j++)
                #pragma unroll
                for (int e = 0; e < 4; e++) acc[m][j][e] = 0.0f;

        #pragma unroll
        for (int c = 0; c < 8; c++) {
            const int buf = c & 1;
            if (c < 7) cpB(c + 1, buf ^ 1);

            const uint32_t aA = aAddr + (uint32_t)(c * 64);
            const uint32_t bB = bAddr + (uint32_t)(buf * SB_SZ);
            #pragma unroll
            for (int ks = 0; ks < 2; ks++) {
                uint32_t ah[2][4];
                ldsm4(ah[0], aA + ks * 32);
                ldsm4(ah[1], aA + 16 * SA_ROW + ks * 32);
                #pragma unroll
                for (int ntp = 0; ntp < 2; ntp++) {
                    uint32_t bf[4];
                    ldsm4(bf, bB + ntp * (16 * 80) + ks * 32);
                    #pragma unroll
                    for (int mt = 0; mt < 2; mt++) {
                        mma16816(acc[mt][ntp * 2 + 0], ah[mt], bf[0], bf[2]);
                        mma16816(acc[mt][ntp * 2 + 1], ah[mt], bf[1], bf[3]);
                    }
                }
            }
            if (c < 7) {
                CP_WAIT(0);
                __syncthreads();
            }
        }

        // per-pass tanh + score partials (held in registers across passes)
        #pragma unroll
        for (int mt = 0; mt < 2; mt++) {
            #pragma unroll
            for (int h = 0; h < 2; h++) {
                float part = 0.0f;
                #pragma unroll
                for (int j = 0; j < 4; j++) {
                    const int col = pass * 128 + wc * 32 + j * 8 +
                                    (lane & 3) * 2;
                    float2 bb = *reinterpret_cast<const float2*>(&sbias[col]);
                    float2 ws = *reinterpret_cast<const float2*>(&ssw[col]);
                    part = fmaf(tanh_mufu(acc[mt][j][h * 2 + 0] + bb.x),
                                ws.x, part);
                    part = fmaf(tanh_mufu(acc[mt][j][h * 2 + 1] + bb.y),
                                ws.y, part);
                }
                partAcc[mt][h] += part;
            }
        }
    }

    // final cross-lane + cross-warp reduce
    float* sred = (float*)(smem + SRED);
    #pragma unroll
    for (int mt = 0; mt < 2; mt++) {
        #pragma unroll
        for (int h = 0; h < 2; h++) {
            float part = partAcc[mt][h];
            part += __shfl_xor_sync(0xffffffffu, part, 1);
            part += __shfl_xor_sync(0xffffffffu, part, 2);
            const int lrow_out = wr * 32 + mt * 16 + (lane >> 2) + h * 8;
            if ((lane & 3) == 0) sred[wc * 64 + lrow_out] = part;
        }
    }
    __syncthreads();
    if (tid < 64)
        g_e[row0 + tid] = (sred[tid] + sred[64 + tid]) +
                          (sred[128 + tid] + sred[192 + tid]);
}

// ---------------------------------------------------------------------------
// Kernel B: chunked causal softmax prefix average with carried scan state.
// ---------------------------------------------------------------------------
__global__ __launch_bounds__(256)
void attend_chunk(const float* __restrict__ H, float* __restrict__ C,
                  int t0, int t1, int first)
{
    __shared__ float sal[96];   // alpha (rescale of old state)
    __shared__ float sp[96];    // p = exp(e - m_new)
    __shared__ float siv[96];   // 1/s after step

    const int n   = blockIdx.x;
    const int tid = threadIdx.x;
    const int len = t1 - t0;

    if (tid < len)
        sal[tid] = g_e[(size_t)(t0 + tid) * NN + n];
    __syncthreads();

    if (tid == 0) {
        float m = first ? -INFINITY : g_m[n];
        float s = first ? 0.0f      : g_s[n];
        for (int i = 0; i < len; i++) {
            float e  = sal[i];
            float mn = fmaxf(m, e);
            float a  = __expf(m - mn);
            float p  = __expf(e - mn);
            s = s * a + p;
            sal[i] = a;
            sp[i]  = p;
            siv[i] = __fdividef(1.0f, s);
            m = mn;
        }
        g_m[n] = m;
        g_s[n] = s;
    }
    __syncthreads();

    const size_t stride = (size_t)NN * DD;
    const float* hp = H + (size_t)(t0) * stride + (size_t)n * DD + tid;
    float*       cp = C + (size_t)(t0) * stride + (size_t)n * DD + tid;

    float num = first ? 0.0f : g_num[n * DD + tid];
    #pragma unroll 4
    for (int i = 0; i < len; i++) {
        float h = __ldcs(hp + (size_t)i * stride);
        num = fmaf(num, sal[i], sp[i] * h);
        __stcs(cp + (size_t)i * stride, num * siv[i]);
    }
    g_num[n * DD + tid] = num;
}

// ---------------------------------------------------------------------------
// Stream/event plumbing (global ctor; no device-memory APIs).
// ---------------------------------------------------------------------------
#define NCHUNK 8
namespace {
struct Plumbing {
    cudaStream_t s2;
    cudaEvent_t  evG[NCHUNK];
    cudaEvent_t  evJ;
    Plumbing() {
        int lo = 0, hi = 0;
        cudaDeviceGetStreamPriorityRange(&lo, &hi);
        cudaStreamCreateWithPriority(&s2, cudaStreamNonBlocking, hi);
        for (int i = 0; i < NCHUNK; i++)
            cudaEventCreateWithFlags(&evG[i], cudaEventDisableTiming);
        cudaEventCreateWithFlags(&evJ, cudaEventDisableTiming);
    }
};
Plumbing g_plumb;
}

// 3 CTAs/SM -> 444 blocks/wave; chunks of 1328 (~3 waves, /16-aligned).
static const int kBlk[NCHUNK + 1] =
    {0, 1328, 2656, 3984, 5312, 6640, 7968, 8096, 8192};

// ---------------------------------------------------------------------------
extern "C" void kernel_launch(void* const* d_in, const int* in_sizes, int n_in,
                              void* d_out, int out_size)
{
    const float* H  = (const float*)d_in[0];
    const float* W  = (const float*)d_in[1];
    const float* b  = (const float*)d_in[2];
    const float* sv = (const float*)d_in[3];
    float* C = (float*)d_out;

    cudaFuncSetAttribute(gemm_score_hmma,
                         cudaFuncAttributeMaxDynamicSharedMemorySize, SMTOT);

    w_prep<<<16, 512>>>(W);

    for (int c = 0; c < NCHUNK; c++) {
        gemm_score_hmma<<<kBlk[c + 1] - kBlk[c], 256, SMTOT>>>(H, b, sv, kBlk[c]);
        cudaEventRecord(g_plumb.evG[c], 0);
    }
    for (int c = 0; c < NCHUNK; c++) {
        cudaStreamWaitEvent(g_plumb.s2, g_plumb.evG[c], 0);
        attend_chunk<<<NN, 256, 0, g_plumb.s2>>>(H, C, kBlk[c] / 16,
                                                 kBlk[c + 1] / 16, c == 0);
    }
    cudaEventRecord(g_plumb.evJ, g_plumb.s2);
    cudaStreamWaitEvent(0, g_plumb.evJ, 0);
}

// round 13
// speedup vs baseline: 1.2548x; 1.2198x over previous
#include <cuda_runtime.h>
#include <cuda_fp16.h>
#include <math.h>
#include <stdint.h>

#define TT 512
#define NN 1024
#define DD 256
#define M_ROWS (TT * NN)

__device__ float g_e[M_ROWS];
__device__ __align__(16) __half g_Whi[DD * DD];
// attend scan carry (online-softmax state across chunk kernels)
__device__ float g_m[NN];
__device__ float g_s[NN];
__device__ __align__(16) float g_num[NN * DD];

// ---------------------------------------------------------------------------
// SMEM (per CTA, 57344 B -> 3 CTAs/SM = 168 KB; +1.2 KB attend block fits).
// ---------------------------------------------------------------------------
#define SA_OFF  0
#define SA_ROW  528
#define SB_OFF  33792
#define SB_SZ   10240
#define SBIAS   54272
#define SSW     55296
#define SRED    56320
#define SMTOT   57344

// ---------------------------------------------------------------------------
// PTX helpers (baseline ISA only -- toolchain targets sm_103, no tcgen05)
// ---------------------------------------------------------------------------
__device__ __forceinline__ uint32_t smem_u32(const void* p) {
    uint32_t a;
    asm("{ .reg .u64 t; cvta.to.shared.u64 t, %1; cvt.u32.u64 %0, t; }"
        : "=r"(a) : "l"(p));
    return a;
}
__device__ __forceinline__ void cp_async16(uint32_t dst, const void* src) {
    asm volatile("cp.async.cg.shared.global [%0], [%1], 16;"
                 :: "r"(dst), "l"(src) : "memory");
}
#define CP_COMMIT() asm volatile("cp.async.commit_group;" ::: "memory")
#define CP_WAIT(n)  asm volatile("cp.async.wait_group %0;" :: "n"(n) : "memory")

__device__ __forceinline__ void ldsm4(uint32_t* r, uint32_t addr) {
    asm volatile("ldmatrix.sync.aligned.m8n8.x4.shared.b16 {%0,%1,%2,%3}, [%4];"
                 : "=r"(r[0]), "=r"(r[1]), "=r"(r[2]), "=r"(r[3]) : "r"(addr));
}
__device__ __forceinline__ void mma16816(float* c, const uint32_t* a,
                                         uint32_t b0, uint32_t b1) {
    asm volatile(
        "mma.sync.aligned.m16n8k16.row.col.f32.f16.f16.f32 "
        "{%0,%1,%2,%3}, {%4,%5,%6,%7}, {%8,%9}, {%0,%1,%2,%3};"
        : "+f"(c[0]), "+f"(c[1]), "+f"(c[2]), "+f"(c[3])
        : "r"(a[0]), "r"(a[1]), "r"(a[2]), "r"(a[3]), "r"(b0), "r"(b1));
}

// fp32 x8 -> fp16 x8
__device__ __forceinline__ uint4 cvt8hi(const float4& u, const float4& v) {
    __half2 h0 = __floats2half2_rn(u.x, u.y);
    __half2 h1 = __floats2half2_rn(u.z, u.w);
    __half2 h2 = __floats2half2_rn(v.x, v.y);
    __half2 h3 = __floats2half2_rn(v.z, v.w);
    uint4 hi;
    hi.x = *(uint32_t*)&h0; hi.y = *(uint32_t*)&h1;
    hi.z = *(uint32_t*)&h2; hi.w = *(uint32_t*)&h3;
    return hi;
}

// tanh via MUFU (EX2 + RCP), rel err ~1e-6
__device__ __forceinline__ float tanh_mufu(float z) {
    float u = __expf(2.0f * z);
    return 1.0f - __fdividef(2.0f, u + 1.0f);
}

// ---------------------------------------------------------------------------
__global__ void w_prep(const float* __restrict__ W) {
    int i = blockIdx.x * blockDim.x + threadIdx.x;
    const float4* p = reinterpret_cast<const float4*>(W) + i * 2;
    reinterpret_cast<uint4*>(g_Whi)[i] = cvt8hi(p[0], p[1]);
}

// ---------------------------------------------------------------------------
// Kernel A: fp16 HMMA GEMM, BM=64 x BN=256 in two 128-col passes.
// 256 threads, 3 CTAs/SM. IDENTICAL to R12 (regs=80 defines the leftover
// register pool the attend blocks live in).
// ---------------------------------------------------------------------------
__global__ __launch_bounds__(256, 3)
void gemm_score_hmma(const float* __restrict__ H,
                     const float* __restrict__ bias,
                     const float* __restrict__ swt,
                     int blk0)
{
    extern __shared__ char smem[];
    const uint32_t sb = smem_u32(smem);
    const int tid  = threadIdx.x;
    const int lane = tid & 31;
    const int warp = tid >> 5;          // 0..7
    const int wr   = warp & 1;          // row group 32*wr
    const int wc   = warp >> 1;         // col group 32*wc (within pass)
    const int row0 = (blockIdx.x + blk0) * 64;

    ((float*)(smem + SBIAS))[tid] = bias[tid];
    ((float*)(smem + SSW))[tid]   = swt[tid];

    const int lrow = lane & 15;
    const int lkh  = lane >> 4;
    const uint32_t aAddr = sb + SA_OFF +
                           (uint32_t)((wr * 32 + lrow) * SA_ROW + lkh * 16);
    const uint32_t bAddr = sb + SB_OFF +
                           (uint32_t)((wc * 32 + lrow) * 80 + lkh * 16);

    const float* sbias = (const float*)(smem + SBIAS);
    const float* ssw   = (const float*)(smem + SSW);

    float partAcc[2][2] = {{0.0f, 0.0f}, {0.0f, 0.0f}};

    #pragma unroll 1
    for (int pass = 0; pass < 2; pass++) {
        const __half* Bsrc = g_Whi + (size_t)pass * 128 * DD;

        auto cpB = [&](int c, int buf) {
            #pragma unroll
            for (int p = 0; p < 2; p++) {
                int idx = tid + p * 256;
                int r   = idx >> 2;
                int ch  = idx & 3;
                cp_async16(sb + SB_OFF + buf * SB_SZ + r * 80 + ch * 16,
                           Bsrc + (size_t)r * DD + c * 32 + ch * 8);
            }
            CP_COMMIT();
        };

        cpB(0, 0);
        if (pass == 0) {
            #pragma unroll
            for (int i = 0; i < 8; i++) {
                int slot = tid + i * 256;
                int r    = slot >> 5;
                int kseg = slot & 31;
                const float* src = H + (size_t)(row0 + r) * DD + kseg * 8;
                float4 u = *reinterpret_cast<const float4*>(src);
                float4 v = *reinterpret_cast<const float4*>(src + 4);
                *reinterpret_cast<uint4*>(smem + SA_OFF + r * SA_ROW +
                                          kseg * 16) = cvt8hi(u, v);
            }
        }
        CP_WAIT(0);
        __syncthreads();

        float acc[2][4][4];
        #pragma unroll
        for (int m = 0; m < 2; m++)
            #pragma unroll
            for (int j = 0; j < 4; j++)
                #pragma unroll
                for (int e = 0; e < 4; e++) acc[m][j][e] = 0.0f;

        #pragma unroll
        for (int c = 0; c < 8; c++) {
            const int buf = c & 1;
            if (c < 7) cpB(c + 1, buf ^ 1);

            const uint32_t aA = aAddr + (uint32_t)(c * 64);
            const uint32_t bB = bAddr + (uint32_t)(buf * SB_SZ);
            #pragma unroll
            for (int ks = 0; ks < 2; ks++) {
                uint32_t ah[2][4];
                ldsm4(ah[0], aA + ks * 32);
                ldsm4(ah[1], aA + 16 * SA_ROW + ks * 32);
                #pragma unroll
                for (int ntp = 0; ntp < 2; ntp++) {
                    uint32_t bf[4];
                    ldsm4(bf, bB + ntp * (16 * 80) + ks * 32);
                    #pragma unroll
                    for (int mt = 0; mt < 2; mt++) {
                        mma16816(acc[mt][ntp * 2 + 0], ah[mt], bf[0], bf[2]);
                        mma16816(acc[mt][ntp * 2 + 1], ah[mt], bf[1], bf[3]);
                    }
                }
            }
            if (c < 7) {
                CP_WAIT(0);
                __syncthreads();
            }
        }

        #pragma unroll
        for (int mt = 0; mt < 2; mt++) {
            #pragma unroll
            for (int h = 0; h < 2; h++) {
                float part = 0.0f;
                #pragma unroll
                for (int j = 0; j < 4; j++) {
                    const int col = pass * 128 + wc * 32 + j * 8 +
                                    (lane & 3) * 2;
                    float2 bb = *reinterpret_cast<const float2*>(&sbias[col]);
                    float2 ws = *reinterpret_cast<const float2*>(&ssw[col]);
                    part = fmaf(tanh_mufu(acc[mt][j][h * 2 + 0] + bb.x),
                                ws.x, part);
                    part = fmaf(tanh_mufu(acc[mt][j][h * 2 + 1] + bb.y),
                                ws.y, part);
                }
                partAcc[mt][h] += part;
            }
        }
    }

    float* sred = (float*)(smem + SRED);
    #pragma unroll
    for (int mt = 0; mt < 2; mt++) {
        #pragma unroll
        for (int h = 0; h < 2; h++) {
            float part = partAcc[mt][h];
            part += __shfl_xor_sync(0xffffffffu, part, 1);
            part += __shfl_xor_sync(0xffffffffu, part, 2);
            const int lrow_out = wr * 32 + mt * 16 + (lane >> 2) + h * 8;
            if ((lane & 3) == 0) sred[wc * 64 + lrow_out] = part;
        }
    }
    __syncthreads();
    if (tid < 64)
        g_e[row0 + tid] = (sred[tid] + sred[64 + tid]) +
                          (sred[128 + tid] + sred[192 + tid]);
}

// ---------------------------------------------------------------------------
// Kernel B: chunked causal softmax prefix average, SLIM: 64 threads,
// float4 per thread, <=64 regs (launch_bounds) so one block co-resides
// with 3 GEMM CTAs (leftover 4K regs / 1.2KB smem / 64 threads).
// ---------------------------------------------------------------------------
__global__ __launch_bounds__(64, 16)
void attend_chunk(const float* __restrict__ H, float* __restrict__ C,
                  int t0, int t1, int first)
{
    __shared__ float sal[96];   // alpha
    __shared__ float sp[96];    // p
    __shared__ float siv[96];   // 1/s

    const int n   = blockIdx.x;
    const int tid = threadIdx.x;
    const int len = t1 - t0;

    for (int i = tid; i < len; i += 64)
        sal[i] = g_e[(size_t)(t0 + i) * NN + n];
    __syncthreads();

    if (tid == 0) {
        float m = first ? -INFINITY : g_m[n];
        float s = first ? 0.0f      : g_s[n];
        for (int i = 0; i < len; i++) {
            float e  = sal[i];
            float mn = fmaxf(m, e);
            float a  = __expf(m - mn);
            float p  = __expf(e - mn);
            s = s * a + p;
            sal[i] = a;
            sp[i]  = p;
            siv[i] = __fdividef(1.0f, s);
            m = mn;
        }
        g_m[n] = m;
        g_s[n] = s;
    }
    __syncthreads();

    const size_t stride4 = (size_t)NN * (DD / 4);   // float4 per t
    const float4* hp = reinterpret_cast<const float4*>(H) +
                       (size_t)t0 * stride4 + (size_t)n * (DD / 4) + tid;
    float4* cp = reinterpret_cast<float4*>(C) +
                 (size_t)t0 * stride4 + (size_t)n * (DD / 4) + tid;
    float4* gn = reinterpret_cast<float4*>(g_num) + (size_t)n * (DD / 4) + tid;

    float4 num;
    if (first) num = make_float4(0.f, 0.f, 0.f, 0.f);
    else       num = *gn;

    #pragma unroll 8
    for (int i = 0; i < len; i++) {
        float4 h = hp[(size_t)i * stride4];
        float a = sal[i], p = sp[i], si = siv[i];
        num.x = fmaf(num.x, a, p * h.x);
        num.y = fmaf(num.y, a, p * h.y);
        num.z = fmaf(num.z, a, p * h.z);
        num.w = fmaf(num.w, a, p * h.w);
        float4 o = make_float4(num.x * si, num.y * si, num.z * si, num.w * si);
        __stcs(cp + (size_t)i * stride4, o);
    }
    *gn = num;
}

// ---------------------------------------------------------------------------
// Stream/event plumbing (global ctor; no device-memory APIs).
// ---------------------------------------------------------------------------
#define NCHUNK 8
namespace {
struct Plumbing {
    cudaStream_t s2;
    cudaEvent_t  evG[NCHUNK];
    cudaEvent_t  evJ;
    Plumbing() {
        int lo = 0, hi = 0;
        cudaDeviceGetStreamPriorityRange(&lo, &hi);
        cudaStreamCreateWithPriority(&s2, cudaStreamNonBlocking, hi);
        for (int i = 0; i < NCHUNK; i++)
            cudaEventCreateWithFlags(&evG[i], cudaEventDisableTiming);
        cudaEventCreateWithFlags(&evJ, cudaEventDisableTiming);
    }
};
Plumbing g_plumb;
}

// 3 CTAs/SM -> 444 blocks/wave; chunks of 1328 (~3 waves, /16-aligned).
static const int kBlk[NCHUNK + 1] =
    {0, 1328, 2656, 3984, 5312, 6640, 7968, 8096, 8192};

// ---------------------------------------------------------------------------
extern "C" void kernel_launch(void* const* d_in, const int* in_sizes, int n_in,
                              void* d_out, int out_size)
{
    const float* H  = (const float*)d_in[0];
    const float* W  = (const float*)d_in[1];
    const float* b  = (const float*)d_in[2];
    const float* sv = (const float*)d_in[3];
    float* C = (float*)d_out;

    cudaFuncSetAttribute(gemm_score_hmma,
                         cudaFuncAttributeMaxDynamicSharedMemorySize, SMTOT);

    w_prep<<<16, 512>>>(W);

    for (int c = 0; c < NCHUNK; c++) {
        gemm_score_hmma<<<kBlk[c + 1] - kBlk[c], 256, SMTOT>>>(H, b, sv, kBlk[c]);
        cudaEventRecord(g_plumb.evG[c], 0);
    }
    for (int c = 0; c < NCHUNK; c++) {
        cudaStreamWaitEvent(g_plumb.s2, g_plumb.evG[c], 0);
        attend_chunk<<<NN, 64, 0, g_plumb.s2>>>(H, C, kBlk[c] / 16,
                                                kBlk[c + 1] / 16, c == 0);
    }
    cudaEventRecord(g_plumb.evJ, g_plumb.s2);
    cudaStreamWaitEvent(0, g_plumb.evJ, 0);
}